// round 1
// baseline (speedup 1.0000x reference)
#include <cuda_runtime.h>
#include <math.h>

#define T_TOK   4096
#define D_DIM   1024
#define H_DIM   512
#define HS_DIM  1024
#define E_NUM   32
#define TOPK    4
#define P_PAIRS (T_TOK*TOPK)   // 16384
#define CAP     2048           // CAP_FACTOR * P / E

// ---------------- scratch (static device globals; no allocation) ----------------
__device__ int   g_pair_e[P_PAIRS];
__device__ float g_pair_w[P_PAIRS];
__device__ int   g_slot_tok[E_NUM*CAP];
__device__ float g_slot_w[E_NUM*CAP];
__device__ int   g_count[E_NUM];
__device__ float g_hexp[(size_t)E_NUM*CAP*H_DIM];   // 134 MB expert hidden
__device__ float g_hsh[(size_t)T_TOK*HS_DIM];       // 16 MB shared-expert hidden

// ---------------- gating: one warp per token ----------------
__global__ __launch_bounds__(256)
void gate_kernel(const float* __restrict__ X, const float* __restrict__ Wg)
{
    int warp = (blockIdx.x*blockDim.x + threadIdx.x) >> 5;
    int lane = threadIdx.x & 31;
    if (warp >= T_TOK) return;
    const float* xr = X + (size_t)warp * D_DIM;
    float xv[32];
    #pragma unroll
    for (int i = 0; i < 32; i++) xv[i] = xr[lane + 32*i];

    float mylogit = 0.f;
    #pragma unroll 1
    for (int e = 0; e < E_NUM; e++) {
        float d = 0.f;
        #pragma unroll
        for (int i = 0; i < 32; i++)
            d += xv[i] * Wg[(size_t)(lane + 32*i)*E_NUM + e];
        #pragma unroll
        for (int off = 16; off; off >>= 1) d += __shfl_xor_sync(0xffffffffu, d, off);
        if (lane == e) mylogit = d;
    }
    // softmax across the 32 lanes (each lane holds one expert's logit)
    float m = mylogit;
    #pragma unroll
    for (int off = 16; off; off >>= 1) m = fmaxf(m, __shfl_xor_sync(0xffffffffu, m, off));
    float p = expf(mylogit - m);
    float s = p;
    #pragma unroll
    for (int off = 16; off; off >>= 1) s += __shfl_xor_sync(0xffffffffu, s, off);
    float prob = p / s;

    // top-4 by repeated warp argmax (lowest index wins ties, like lax.top_k)
    for (int k = 0; k < TOPK; k++) {
        float v = prob; int idx = lane;
        #pragma unroll
        for (int off = 16; off; off >>= 1) {
            float ov = __shfl_xor_sync(0xffffffffu, v, off);
            int   oi = __shfl_xor_sync(0xffffffffu, idx, off);
            if (ov > v || (ov == v && oi < idx)) { v = ov; idx = oi; }
        }
        if (lane == 0) {
            g_pair_e[warp*TOPK + k] = idx;
            g_pair_w[warp*TOPK + k] = v;
        }
        if (lane == idx) prob = -1.f;
    }
}

// ---------------- dispatch: one block per expert, ordered compaction ----------------
__global__ __launch_bounds__(256)
void dispatch_kernel()
{
    int e = blockIdx.x;
    int tid = threadIdx.x;
    int lane = tid & 31, wid = tid >> 5;
    __shared__ int wtot[8];
    __shared__ int s_run;
    if (tid == 0) s_run = 0;
    __syncthreads();

    for (int base = 0; base < P_PAIRS; base += 256) {
        int p = base + tid;                    // P_PAIRS % 256 == 0
        int flag = (g_pair_e[p] == e) ? 1 : 0;
        unsigned b = __ballot_sync(0xffffffffu, flag);
        int woff = __popc(b & ((1u << lane) - 1u));
        if (lane == 0) wtot[wid] = __popc(b);
        __syncthreads();
        int excl = 0, tot = 0;
        #pragma unroll
        for (int w = 0; w < 8; w++) { if (w < wid) excl += wtot[w]; tot += wtot[w]; }
        int pos = s_run + excl + woff;
        if (flag && pos < CAP) {
            g_slot_tok[e*CAP + pos] = p >> 2;      // pair -> token
            g_slot_w  [e*CAP + pos] = g_pair_w[p];
        }
        __syncthreads();
        if (tid == 0) s_run += tot;
        __syncthreads();
    }
    if (tid == 0) g_count[e] = min(s_run, CAP);
}

// ---------------- fused up-proj: H = silu(X@W1) * (X@W3) ----------------
// expert_mode: rows gathered via g_slot_tok, per-expert weights/output.
// shared mode: dense rows 0..T_TOK, output g_hsh.
__global__ __launch_bounds__(256)
void up_kernel(const float* __restrict__ X,
               const float* __restrict__ W1base,
               const float* __restrict__ W3base,
               int NN, int expert_mode)
{
    int e = blockIdx.z;
    int M_eff;
    const int* rows = nullptr;
    const float *W1, *W3;
    float* Hout;
    if (expert_mode) {
        M_eff = g_count[e];
        rows  = g_slot_tok + e*CAP;
        W1    = W1base + (size_t)e*D_DIM*NN;
        W3    = W3base + (size_t)e*D_DIM*NN;
        Hout  = g_hexp + (size_t)e*CAP*NN;
    } else {
        M_eff = T_TOK; W1 = W1base; W3 = W3base; Hout = g_hsh;
    }
    int mbase = blockIdx.x * 64;
    if (mbase >= M_eff) return;
    int nbase = blockIdx.y * 64;

    __shared__ float As[16][64];
    __shared__ float B1s[16][64];
    __shared__ float B3s[16][64];

    int tid = threadIdx.x;
    int tx = tid & 15, ty = tid >> 4;
    float acc1[4][4] = {}, acc3[4][4] = {};

    int arow = tid >> 2;           // 0..63
    int akq  = (tid & 3) * 4;      // k sub-offset
    bool avalid = (mbase + arow) < M_eff;
    int grow = avalid ? (rows ? rows[mbase + arow] : (mbase + arow)) : 0;
    const float* aptr = X + (size_t)grow*D_DIM + akq;

    int brow = tid >> 4;           // 0..15
    int bcol = (tid & 15) * 4;
    const float* b1ptr = W1 + (size_t)brow*NN + nbase + bcol;
    const float* b3ptr = W3 + (size_t)brow*NN + nbase + bcol;

    for (int kt = 0; kt < D_DIM; kt += 16) {
        float4 av = avalid ? *(const float4*)(aptr + kt) : make_float4(0.f,0.f,0.f,0.f);
        As[akq+0][arow] = av.x; As[akq+1][arow] = av.y;
        As[akq+2][arow] = av.z; As[akq+3][arow] = av.w;
        *(float4*)&B1s[brow][bcol] = *(const float4*)(b1ptr + (size_t)kt*NN);
        *(float4*)&B3s[brow][bcol] = *(const float4*)(b3ptr + (size_t)kt*NN);
        __syncthreads();
        #pragma unroll
        for (int kk = 0; kk < 16; kk++) {
            float4 a  = *(const float4*)&As[kk][ty*4];
            float4 b1 = *(const float4*)&B1s[kk][tx*4];
            float4 b3 = *(const float4*)&B3s[kk][tx*4];
            float aa[4]  = {a.x, a.y, a.z, a.w};
            float bb1[4] = {b1.x, b1.y, b1.z, b1.w};
            float bb3[4] = {b3.x, b3.y, b3.z, b3.w};
            #pragma unroll
            for (int i = 0; i < 4; i++)
                #pragma unroll
                for (int j = 0; j < 4; j++) {
                    acc1[i][j] += aa[i]*bb1[j];
                    acc3[i][j] += aa[i]*bb3[j];
                }
        }
        __syncthreads();
    }

    #pragma unroll
    for (int i = 0; i < 4; i++) {
        int m = mbase + ty*4 + i;
        if (m < M_eff) {
            float4 hv;
            float g0 = acc1[i][0], g1 = acc1[i][1], g2 = acc1[i][2], g3 = acc1[i][3];
            hv.x = (g0 / (1.f + expf(-g0))) * acc3[i][0];
            hv.y = (g1 / (1.f + expf(-g1))) * acc3[i][1];
            hv.z = (g2 / (1.f + expf(-g2))) * acc3[i][2];
            hv.w = (g3 / (1.f + expf(-g3))) * acc3[i][3];
            *(float4*)(Hout + (size_t)m*NN + nbase + tx*4) = hv;
        }
    }
}

// ---------------- down-proj: out += w * (H @ W2) ----------------
// shared mode (expert_mode=0): plain dense store to out (initializes every element).
// expert mode: scatter atomicAdd into out at slot's token, scaled by slot weight.
__global__ __launch_bounds__(256)
void down_kernel(const float* __restrict__ W2base,
                 int KK, int expert_mode,
                 float* __restrict__ out)
{
    int e = blockIdx.z;
    int M_eff;
    const int* rows = nullptr;
    const float* wv = nullptr;
    const float *Hin, *W2;
    if (expert_mode) {
        M_eff = g_count[e];
        rows  = g_slot_tok + e*CAP;
        wv    = g_slot_w  + e*CAP;
        W2    = W2base + (size_t)e*KK*D_DIM;
        Hin   = g_hexp + (size_t)e*CAP*KK;
    } else {
        M_eff = T_TOK; W2 = W2base; Hin = g_hsh;
    }
    int mbase = blockIdx.x * 64;
    if (mbase >= M_eff) return;
    int nbase = blockIdx.y * 64;

    __shared__ float As[16][64];
    __shared__ float Bs[16][64];

    int tid = threadIdx.x;
    int tx = tid & 15, ty = tid >> 4;
    float acc[4][4] = {};

    int arow = tid >> 2;
    int akq  = (tid & 3) * 4;
    bool avalid = (mbase + arow) < M_eff;
    const float* aptr = Hin + (size_t)(mbase + arow)*KK + akq;

    int brow = tid >> 4;
    int bcol = (tid & 15) * 4;
    const float* bptr = W2 + (size_t)brow*D_DIM + nbase + bcol;

    for (int kt = 0; kt < KK; kt += 16) {
        float4 av = avalid ? *(const float4*)(aptr + kt) : make_float4(0.f,0.f,0.f,0.f);
        As[akq+0][arow] = av.x; As[akq+1][arow] = av.y;
        As[akq+2][arow] = av.z; As[akq+3][arow] = av.w;
        *(float4*)&Bs[brow][bcol] = *(const float4*)(bptr + (size_t)kt*D_DIM);
        __syncthreads();
        #pragma unroll
        for (int kk = 0; kk < 16; kk++) {
            float4 a = *(const float4*)&As[kk][ty*4];
            float4 b = *(const float4*)&Bs[kk][tx*4];
            float aa[4] = {a.x, a.y, a.z, a.w};
            float bb[4] = {b.x, b.y, b.z, b.w};
            #pragma unroll
            for (int i = 0; i < 4; i++)
                #pragma unroll
                for (int j = 0; j < 4; j++)
                    acc[i][j] += aa[i]*bb[j];
        }
        __syncthreads();
    }

    #pragma unroll
    for (int i = 0; i < 4; i++) {
        int m = mbase + ty*4 + i;
        if (m < M_eff) {
            float scale = wv ? wv[m] : 1.f;
            int tok = rows ? rows[m] : m;
            float* orow = out + (size_t)tok*D_DIM + nbase + tx*4;
            if (rows) {
                #pragma unroll
                for (int j = 0; j < 4; j++)
                    atomicAdd(&orow[j], acc[i][j] * scale);
            } else {
                float4 v;
                v.x = acc[i][0]; v.y = acc[i][1]; v.z = acc[i][2]; v.w = acc[i][3];
                *(float4*)orow = v;
            }
        }
    }
}

// ---------------- host launcher ----------------
extern "C" void kernel_launch(void* const* d_in, const int* in_sizes, int n_in,
                              void* d_out, int out_size)
{
    const float* x   = (const float*)d_in[0];
    const float* Wg  = (const float*)d_in[1];
    const float* W1  = (const float*)d_in[2];
    const float* W2  = (const float*)d_in[3];
    const float* W3  = (const float*)d_in[4];
    const float* Ws1 = (const float*)d_in[5];
    const float* Ws2 = (const float*)d_in[6];
    const float* Ws3 = (const float*)d_in[7];
    float* out = (float*)d_out;

    // 1. gating (4096 warps)
    gate_kernel<<<T_TOK/8, 256>>>(x, Wg);

    // 2. ordered dispatch per expert
    dispatch_kernel<<<E_NUM, 256>>>();

    // 3. shared expert up: [4096,1024] @ [1024,1024] x2 fused
    {
        dim3 g(T_TOK/64, HS_DIM/64, 1);
        up_kernel<<<g, 256>>>(x, Ws1, Ws3, HS_DIM, 0);
    }
    // 4. shared expert down: dense store into out (covers all elements)
    {
        dim3 g(T_TOK/64, D_DIM/64, 1);
        down_kernel<<<g, 256>>>(Ws2, HS_DIM, 0, out);
    }
    // 5. routed experts up (gathered rows)
    {
        dim3 g(CAP/64, H_DIM/64, E_NUM);
        up_kernel<<<g, 256>>>(x, W1, W3, H_DIM, 1);
    }
    // 6. routed experts down: weighted scatter-add into out
    {
        dim3 g(CAP/64, D_DIM/64, E_NUM);
        down_kernel<<<g, 256>>>(W2, H_DIM, 1, out);
    }
}

// round 2
// speedup vs baseline: 1.5501x; 1.5501x over previous
#include <cuda_runtime.h>
#include <cuda_bf16.h>
#include <math.h>
#include <stdint.h>

#define T_TOK   4096
#define D_DIM   1024
#define H_DIM   512
#define HS_DIM  1024
#define E_NUM   32
#define TOPK    4
#define P_PAIRS (T_TOK*TOPK)   // 16384
#define CAP     2048

#define BM 128
#define BN 64
#define BK 32
#define ASTR 40   // 32 + 8 pad halves -> 80B row stride (conflict-free ldmatrix)
#define BSTR 72   // 64 + 8 pad halves -> 144B row stride (conflict-free ldmatrix.trans)

// ---------------- scratch (static device globals; no allocation) ----------------
__device__ int   g_pair_e[P_PAIRS];
__device__ float g_pair_w[P_PAIRS];
__device__ int   g_slot_tok[E_NUM*CAP];
__device__ float g_slot_w[E_NUM*CAP];
__device__ int   g_count[E_NUM];
__device__ __align__(16) __nv_bfloat16 g_hexp_hi[(size_t)E_NUM*CAP*H_DIM];
__device__ __align__(16) __nv_bfloat16 g_hexp_lo[(size_t)E_NUM*CAP*H_DIM];
__device__ __align__(16) __nv_bfloat16 g_hsh_hi[(size_t)T_TOK*HS_DIM];
__device__ __align__(16) __nv_bfloat16 g_hsh_lo[(size_t)T_TOK*HS_DIM];

// ---------------- small helpers ----------------
__device__ __forceinline__ uint32_t smem_u32(const void* p) {
    return (uint32_t)__cvta_generic_to_shared(p);
}
__device__ __forceinline__ void ldsm_x4(uint32_t* r, uint32_t a) {
    asm volatile("ldmatrix.sync.aligned.m8n8.x4.shared.b16 {%0,%1,%2,%3}, [%4];"
        : "=r"(r[0]), "=r"(r[1]), "=r"(r[2]), "=r"(r[3]) : "r"(a));
}
__device__ __forceinline__ void ldsm_x4_t(uint32_t* r, uint32_t a) {
    asm volatile("ldmatrix.sync.aligned.m8n8.x4.trans.shared.b16 {%0,%1,%2,%3}, [%4];"
        : "=r"(r[0]), "=r"(r[1]), "=r"(r[2]), "=r"(r[3]) : "r"(a));
}
__device__ __forceinline__ void mma16816(float* c, const uint32_t* a, const uint32_t* b) {
    asm volatile(
        "mma.sync.aligned.m16n8k16.row.col.f32.bf16.bf16.f32 "
        "{%0,%1,%2,%3}, {%4,%5,%6,%7}, {%8,%9}, {%0,%1,%2,%3};"
        : "+f"(c[0]), "+f"(c[1]), "+f"(c[2]), "+f"(c[3])
        : "r"(a[0]), "r"(a[1]), "r"(a[2]), "r"(a[3]), "r"(b[0]), "r"(b[1]));
}
__device__ __forceinline__ void split_bf16(float x, uint16_t& h, uint16_t& l) {
    __nv_bfloat16 hb = __float2bfloat16(x);
    float r = x - __bfloat162float(hb);
    __nv_bfloat16 lb = __float2bfloat16(r);
    h = __bfloat16_as_ushort(hb);
    l = __bfloat16_as_ushort(lb);
}
__device__ __forceinline__ void pack4(float4 v, uint2& hp, uint2& lp) {
    uint16_t hx,lx,hy,ly,hz,lz,hw,lw;
    split_bf16(v.x,hx,lx); split_bf16(v.y,hy,ly);
    split_bf16(v.z,hz,lz); split_bf16(v.w,hw,lw);
    hp = make_uint2((uint32_t)hx | ((uint32_t)hy<<16), (uint32_t)hz | ((uint32_t)hw<<16));
    lp = make_uint2((uint32_t)lx | ((uint32_t)ly<<16), (uint32_t)lz | ((uint32_t)lw<<16));
}

// ---------------- gating: one warp per token ----------------
__global__ __launch_bounds__(256)
void gate_kernel(const float* __restrict__ X, const float* __restrict__ Wg)
{
    int warp = (blockIdx.x*blockDim.x + threadIdx.x) >> 5;
    int lane = threadIdx.x & 31;
    if (warp >= T_TOK) return;
    const float* xr = X + (size_t)warp * D_DIM;
    float xv[32];
    #pragma unroll
    for (int i = 0; i < 32; i++) xv[i] = xr[lane + 32*i];

    float mylogit = 0.f;
    #pragma unroll 1
    for (int e = 0; e < E_NUM; e++) {
        float d = 0.f;
        #pragma unroll
        for (int i = 0; i < 32; i++)
            d += xv[i] * Wg[(size_t)(lane + 32*i)*E_NUM + e];
        #pragma unroll
        for (int off = 16; off; off >>= 1) d += __shfl_xor_sync(0xffffffffu, d, off);
        if (lane == e) mylogit = d;
    }
    float m = mylogit;
    #pragma unroll
    for (int off = 16; off; off >>= 1) m = fmaxf(m, __shfl_xor_sync(0xffffffffu, m, off));
    float p = expf(mylogit - m);
    float s = p;
    #pragma unroll
    for (int off = 16; off; off >>= 1) s += __shfl_xor_sync(0xffffffffu, s, off);
    float prob = p / s;

    for (int k = 0; k < TOPK; k++) {
        float v = prob; int idx = lane;
        #pragma unroll
        for (int off = 16; off; off >>= 1) {
            float ov = __shfl_xor_sync(0xffffffffu, v, off);
            int   oi = __shfl_xor_sync(0xffffffffu, idx, off);
            if (ov > v || (ov == v && oi < idx)) { v = ov; idx = oi; }
        }
        if (lane == 0) {
            g_pair_e[warp*TOPK + k] = idx;
            g_pair_w[warp*TOPK + k] = v;
        }
        if (lane == idx) prob = -1.f;
    }
}

// ---------------- dispatch: one block per expert, ordered compaction ----------------
__global__ __launch_bounds__(256)
void dispatch_kernel()
{
    int e = blockIdx.x;
    int tid = threadIdx.x;
    int lane = tid & 31, wid = tid >> 5;
    __shared__ int wtot[8];
    __shared__ int s_run;
    if (tid == 0) s_run = 0;
    __syncthreads();

    for (int base = 0; base < P_PAIRS; base += 256) {
        int p = base + tid;
        int flag = (g_pair_e[p] == e) ? 1 : 0;
        unsigned b = __ballot_sync(0xffffffffu, flag);
        int woff = __popc(b & ((1u << lane) - 1u));
        if (lane == 0) wtot[wid] = __popc(b);
        __syncthreads();
        int excl = 0, tot = 0;
        #pragma unroll
        for (int w = 0; w < 8; w++) { if (w < wid) excl += wtot[w]; tot += wtot[w]; }
        int pos = s_run + excl + woff;
        if (flag && pos < CAP) {
            g_slot_tok[e*CAP + pos] = p >> 2;
            g_slot_w  [e*CAP + pos] = g_pair_w[p];
        }
        __syncthreads();
        if (tid == 0) s_run += tot;
        __syncthreads();
    }
    if (tid == 0) g_count[e] = min(s_run, CAP);
}

// ---------------- fused up-proj (tensor): H = silu(X@W1) * (X@W3), bf16x3 split ----
__global__ __launch_bounds__(256)
void up_mma(const float* __restrict__ X,
            const float* __restrict__ W1g,
            const float* __restrict__ W3g,
            int NN, int expert_mode)
{
    __shared__ __align__(16) __nv_bfloat16 Ah[BM][ASTR], Al[BM][ASTR];
    __shared__ __align__(16) __nv_bfloat16 B1h[BK][BSTR], B1l[BK][BSTR];
    __shared__ __align__(16) __nv_bfloat16 B3h[BK][BSTR], B3l[BK][BSTR];

    int e = blockIdx.z;
    int M_eff; const int* rows = nullptr;
    const float *W1, *W3; __nv_bfloat16 *Hhi, *Hlo;
    if (expert_mode) {
        M_eff = g_count[e];
        rows  = g_slot_tok + e*CAP;
        W1 = W1g + (size_t)e*D_DIM*NN;
        W3 = W3g + (size_t)e*D_DIM*NN;
        Hhi = g_hexp_hi + (size_t)e*CAP*NN;
        Hlo = g_hexp_lo + (size_t)e*CAP*NN;
    } else {
        M_eff = T_TOK; W1 = W1g; W3 = W3g; Hhi = g_hsh_hi; Hlo = g_hsh_lo;
    }
    int mbase = blockIdx.x * BM;
    if (mbase >= M_eff) return;
    int nbase = blockIdx.y * BN;

    int tid = threadIdx.x, lane = tid & 31, wid = tid >> 5;
    int wm = wid >> 1, wn = wid & 1;

    // staging assignment
    int ar = tid >> 1, ac = (tid & 1) * 16;
    bool avalid = (mbase + ar) < M_eff;
    int grow = avalid ? (rows ? rows[mbase + ar] : (mbase + ar)) : 0;
    const float* aptr = X + (size_t)grow * D_DIM + ac;
    int br = tid >> 3, bc = (tid & 7) * 8;
    const float* b1p = W1 + (size_t)br * NN + nbase + bc;
    const float* b3p = W3 + (size_t)br * NN + nbase + bc;

    float4 a_nx[4], b1_nx[2], b3_nx[2];

    auto loadk = [&](int kt) {
        #pragma unroll
        for (int j = 0; j < 4; j++)
            a_nx[j] = avalid ? *(const float4*)(aptr + kt + j*4)
                             : make_float4(0.f,0.f,0.f,0.f);
        #pragma unroll
        for (int j = 0; j < 2; j++) {
            b1_nx[j] = *(const float4*)(b1p + (size_t)kt*NN + j*4);
            b3_nx[j] = *(const float4*)(b3p + (size_t)kt*NN + j*4);
        }
    };
    auto storek = [&]() {
        #pragma unroll
        for (int j = 0; j < 4; j++) {
            uint2 hp, lp; pack4(a_nx[j], hp, lp);
            *(uint2*)&Ah[ar][ac + 4*j] = hp;
            *(uint2*)&Al[ar][ac + 4*j] = lp;
        }
        #pragma unroll
        for (int j = 0; j < 2; j++) {
            uint2 hp, lp;
            pack4(b1_nx[j], hp, lp);
            *(uint2*)&B1h[br][bc + 4*j] = hp;
            *(uint2*)&B1l[br][bc + 4*j] = lp;
            pack4(b3_nx[j], hp, lp);
            *(uint2*)&B3h[br][bc + 4*j] = hp;
            *(uint2*)&B3l[br][bc + 4*j] = lp;
        }
    };

    float c1[2][4][4] = {}, c3[2][4][4] = {};

    loadk(0); storek(); __syncthreads();

    for (int kt = 0; kt < D_DIM; kt += BK) {
        bool more = (kt + BK) < D_DIM;
        if (more) loadk(kt + BK);
        #pragma unroll
        for (int ks = 0; ks < 2; ks++) {
            int k0 = ks * 16;
            uint32_t ah[2][4], al[2][4];
            #pragma unroll
            for (int mt = 0; mt < 2; mt++) {
                int r = wm*32 + mt*16 + (lane & 15);
                int c = k0 + (lane >> 4) * 8;
                ldsm_x4(ah[mt], smem_u32(&Ah[r][c]));
                ldsm_x4(al[mt], smem_u32(&Al[r][c]));
            }
            uint32_t b1hf[4][2], b1lf[4][2], b3hf[4][2], b3lf[4][2];
            #pragma unroll
            for (int h = 0; h < 2; h++) {
                int rr = k0 + (lane & 7) + ((lane >> 3) & 1) * 8;
                int cc = wn*32 + h*16 + (lane >> 4) * 8;
                uint32_t t4[4];
                ldsm_x4_t(t4, smem_u32(&B1h[rr][cc]));
                b1hf[h*2][0]=t4[0]; b1hf[h*2][1]=t4[1]; b1hf[h*2+1][0]=t4[2]; b1hf[h*2+1][1]=t4[3];
                ldsm_x4_t(t4, smem_u32(&B1l[rr][cc]));
                b1lf[h*2][0]=t4[0]; b1lf[h*2][1]=t4[1]; b1lf[h*2+1][0]=t4[2]; b1lf[h*2+1][1]=t4[3];
                ldsm_x4_t(t4, smem_u32(&B3h[rr][cc]));
                b3hf[h*2][0]=t4[0]; b3hf[h*2][1]=t4[1]; b3hf[h*2+1][0]=t4[2]; b3hf[h*2+1][1]=t4[3];
                ldsm_x4_t(t4, smem_u32(&B3l[rr][cc]));
                b3lf[h*2][0]=t4[0]; b3lf[h*2][1]=t4[1]; b3lf[h*2+1][0]=t4[2]; b3lf[h*2+1][1]=t4[3];
            }
            #pragma unroll
            for (int mt = 0; mt < 2; mt++)
                #pragma unroll
                for (int nt = 0; nt < 4; nt++) {
                    mma16816(c1[mt][nt], ah[mt], b1hf[nt]);
                    mma16816(c1[mt][nt], ah[mt], b1lf[nt]);
                    mma16816(c1[mt][nt], al[mt], b1hf[nt]);
                    mma16816(c3[mt][nt], ah[mt], b3hf[nt]);
                    mma16816(c3[mt][nt], ah[mt], b3lf[nt]);
                    mma16816(c3[mt][nt], al[mt], b3hf[nt]);
                }
        }
        __syncthreads();
        if (more) storek();
        __syncthreads();
    }

    // epilogue: silu(c1)*c3 -> bf16 hi/lo pair store
    int r0 = lane >> 2, cb = (lane & 3) * 2;
    #pragma unroll
    for (int mt = 0; mt < 2; mt++)
        #pragma unroll
        for (int nt = 0; nt < 4; nt++) {
            int n = nbase + wn*32 + nt*8 + cb;
            #pragma unroll
            for (int p = 0; p < 2; p++) {
                int m = mbase + wm*32 + mt*16 + r0 + p*8;
                if (m < M_eff) {
                    float g0 = c1[mt][nt][2*p+0], g1 = c1[mt][nt][2*p+1];
                    float v0 = g0 / (1.f + expf(-g0)) * c3[mt][nt][2*p+0];
                    float v1 = g1 / (1.f + expf(-g1)) * c3[mt][nt][2*p+1];
                    uint16_t h0,l0,h1,l1;
                    split_bf16(v0,h0,l0); split_bf16(v1,h1,l1);
                    *(uint32_t*)&Hhi[(size_t)m*NN + n] = (uint32_t)h0 | ((uint32_t)h1<<16);
                    *(uint32_t*)&Hlo[(size_t)m*NN + n] = (uint32_t)l0 | ((uint32_t)l1<<16);
                }
            }
        }
}

// ---------------- down-proj (tensor): out (+)= w * (H @ W2), bf16x3 split -------
__global__ __launch_bounds__(256)
void down_mma(const float* __restrict__ W2g, int KK, int expert_mode,
              float* __restrict__ out)
{
    __shared__ __align__(16) __nv_bfloat16 Ah[BM][ASTR], Al[BM][ASTR];
    __shared__ __align__(16) __nv_bfloat16 Bh[BK][BSTR], Bl[BK][BSTR];

    int e = blockIdx.z;
    int M_eff; const int* rows = nullptr; const float* wv = nullptr;
    const float* W2; const __nv_bfloat16 *HhiP, *HloP;
    if (expert_mode) {
        M_eff = g_count[e];
        rows  = g_slot_tok + e*CAP;
        wv    = g_slot_w  + e*CAP;
        W2    = W2g + (size_t)e*KK*D_DIM;
        HhiP  = g_hexp_hi + (size_t)e*CAP*KK;
        HloP  = g_hexp_lo + (size_t)e*CAP*KK;
    } else {
        M_eff = T_TOK; W2 = W2g; HhiP = g_hsh_hi; HloP = g_hsh_lo;
    }
    int mbase = blockIdx.x * BM;
    if (mbase >= M_eff) return;
    int nbase = blockIdx.y * BN;

    int tid = threadIdx.x, lane = tid & 31, wid = tid >> 5;
    int wm = wid >> 1, wn = wid & 1;

    int ar = tid >> 1, ah_half = tid & 1;
    bool avalid = (mbase + ar) < M_eff;
    const __nv_bfloat16* ahp = HhiP + (size_t)(mbase + ar)*KK + ah_half*16;
    const __nv_bfloat16* alp = HloP + (size_t)(mbase + ar)*KK + ah_half*16;
    int br = tid >> 3, bc = (tid & 7) * 8;
    const float* bp = W2 + (size_t)br * D_DIM + nbase + bc;

    uint4 a_nx_h[2], a_nx_l[2];
    float4 b_nx[2];

    auto loadk = [&](int kt) {
        #pragma unroll
        for (int j = 0; j < 2; j++) {
            if (avalid) {
                a_nx_h[j] = *(const uint4*)(ahp + kt + 8*j);
                a_nx_l[j] = *(const uint4*)(alp + kt + 8*j);
            } else {
                a_nx_h[j] = make_uint4(0,0,0,0);
                a_nx_l[j] = make_uint4(0,0,0,0);
            }
            b_nx[j] = *(const float4*)(bp + (size_t)kt*D_DIM + j*4);
        }
    };
    auto storek = [&]() {
        #pragma unroll
        for (int j = 0; j < 2; j++) {
            *(uint4*)&Ah[ar][ah_half*16 + 8*j] = a_nx_h[j];
            *(uint4*)&Al[ar][ah_half*16 + 8*j] = a_nx_l[j];
            uint2 hp, lp; pack4(b_nx[j], hp, lp);
            *(uint2*)&Bh[br][bc + 4*j] = hp;
            *(uint2*)&Bl[br][bc + 4*j] = lp;
        }
    };

    float c[2][4][4] = {};

    loadk(0); storek(); __syncthreads();

    for (int kt = 0; kt < KK; kt += BK) {
        bool more = (kt + BK) < KK;
        if (more) loadk(kt + BK);
        #pragma unroll
        for (int ks = 0; ks < 2; ks++) {
            int k0 = ks * 16;
            uint32_t ah[2][4], al[2][4];
            #pragma unroll
            for (int mt = 0; mt < 2; mt++) {
                int r = wm*32 + mt*16 + (lane & 15);
                int cc = k0 + (lane >> 4) * 8;
                ldsm_x4(ah[mt], smem_u32(&Ah[r][cc]));
                ldsm_x4(al[mt], smem_u32(&Al[r][cc]));
            }
            uint32_t bhf[4][2], blf[4][2];
            #pragma unroll
            for (int h = 0; h < 2; h++) {
                int rr = k0 + (lane & 7) + ((lane >> 3) & 1) * 8;
                int cc = wn*32 + h*16 + (lane >> 4) * 8;
                uint32_t t4[4];
                ldsm_x4_t(t4, smem_u32(&Bh[rr][cc]));
                bhf[h*2][0]=t4[0]; bhf[h*2][1]=t4[1]; bhf[h*2+1][0]=t4[2]; bhf[h*2+1][1]=t4[3];
                ldsm_x4_t(t4, smem_u32(&Bl[rr][cc]));
                blf[h*2][0]=t4[0]; blf[h*2][1]=t4[1]; blf[h*2+1][0]=t4[2]; blf[h*2+1][1]=t4[3];
            }
            #pragma unroll
            for (int mt = 0; mt < 2; mt++)
                #pragma unroll
                for (int nt = 0; nt < 4; nt++) {
                    mma16816(c[mt][nt], ah[mt], bhf[nt]);
                    mma16816(c[mt][nt], ah[mt], blf[nt]);
                    mma16816(c[mt][nt], al[mt], bhf[nt]);
                }
        }
        __syncthreads();
        if (more) storek();
        __syncthreads();
    }

    int r0 = lane >> 2, cb = (lane & 3) * 2;
    #pragma unroll
    for (int mt = 0; mt < 2; mt++)
        #pragma unroll
        for (int nt = 0; nt < 4; nt++) {
            int n = nbase + wn*32 + nt*8 + cb;
            #pragma unroll
            for (int p = 0; p < 2; p++) {
                int m = mbase + wm*32 + mt*16 + r0 + p*8;
                if (m < M_eff) {
                    float v0 = c[mt][nt][2*p+0], v1 = c[mt][nt][2*p+1];
                    if (expert_mode) {
                        int tok = rows[m];
                        float w = wv[m];
                        float* orow = out + (size_t)tok*D_DIM + n;
                        atomicAdd(&orow[0], v0 * w);
                        atomicAdd(&orow[1], v1 * w);
                    } else {
                        *(float2*)(out + (size_t)m*D_DIM + n) = make_float2(v0, v1);
                    }
                }
            }
        }
}

// ---------------- host launcher ----------------
extern "C" void kernel_launch(void* const* d_in, const int* in_sizes, int n_in,
                              void* d_out, int out_size)
{
    const float* x   = (const float*)d_in[0];
    const float* Wg  = (const float*)d_in[1];
    const float* W1  = (const float*)d_in[2];
    const float* W2  = (const float*)d_in[3];
    const float* W3  = (const float*)d_in[4];
    const float* Ws1 = (const float*)d_in[5];
    const float* Ws2 = (const float*)d_in[6];
    const float* Ws3 = (const float*)d_in[7];
    float* out = (float*)d_out;

    gate_kernel<<<T_TOK/8, 256>>>(x, Wg);
    dispatch_kernel<<<E_NUM, 256>>>();

    // shared expert (dense) — down stores initialize every out element
    up_mma  <<<dim3(T_TOK/BM, HS_DIM/BN, 1), 256>>>(x, Ws1, Ws3, HS_DIM, 0);
    down_mma<<<dim3(T_TOK/BM, D_DIM/BN, 1), 256>>>(Ws2, HS_DIM, 0, out);

    // routed experts — down scatter-adds on top
    up_mma  <<<dim3(CAP/BM, H_DIM/BN, E_NUM), 256>>>(x, W1, W3, H_DIM, 1);
    down_mma<<<dim3(CAP/BM, D_DIM/BN, E_NUM), 256>>>(W2, H_DIM, 1, out);
}

// round 3
// speedup vs baseline: 1.8681x; 1.2052x over previous
#include <cuda_runtime.h>
#include <cuda_bf16.h>
#include <math.h>
#include <stdint.h>

#define T_TOK   4096
#define D_DIM   1024
#define H_DIM   512
#define HS_DIM  1024
#define E_NUM   32
#define TOPK    4
#define P_PAIRS (T_TOK*TOPK)
#define CAP     2048

#define BM 128
#define BN 64
#define BK 32
#define ASTR 40               // halves: 80B row stride
#define BSTR 72               // halves: 144B row stride
#define SA (BM*ASTR)          // 5120 halves per A matrix per stage
#define SB (BK*BSTR)          // 2304 halves per B matrix per stage
#define UP_SMEM_BYTES   ((4*SA + 8*SB)*2)   // 77824
#define DOWN_SMEM_BYTES ((4*SA + 4*SB)*2)   // 59392

// ---------------- scratch ----------------
__device__ int   g_pair_e[P_PAIRS];
__device__ float g_pair_w[P_PAIRS];
__device__ int   g_slot_tok[E_NUM*CAP];
__device__ float g_slot_w[E_NUM*CAP];
__device__ int   g_count[E_NUM];
__device__ __align__(16) __nv_bfloat16 g_hexp_hi[(size_t)E_NUM*CAP*H_DIM];
__device__ __align__(16) __nv_bfloat16 g_hexp_lo[(size_t)E_NUM*CAP*H_DIM];
__device__ __align__(16) __nv_bfloat16 g_hsh_hi[(size_t)T_TOK*HS_DIM];
__device__ __align__(16) __nv_bfloat16 g_hsh_lo[(size_t)T_TOK*HS_DIM];
// pre-split operands
__device__ __align__(16) __nv_bfloat16 g_Xh[(size_t)T_TOK*D_DIM],  g_Xl[(size_t)T_TOK*D_DIM];
__device__ __align__(16) __nv_bfloat16 g_W1h[(size_t)E_NUM*D_DIM*H_DIM], g_W1l[(size_t)E_NUM*D_DIM*H_DIM];
__device__ __align__(16) __nv_bfloat16 g_W3h[(size_t)E_NUM*D_DIM*H_DIM], g_W3l[(size_t)E_NUM*D_DIM*H_DIM];
__device__ __align__(16) __nv_bfloat16 g_W2h[(size_t)E_NUM*H_DIM*D_DIM], g_W2l[(size_t)E_NUM*H_DIM*D_DIM];
__device__ __align__(16) __nv_bfloat16 g_Ws1h[(size_t)D_DIM*HS_DIM], g_Ws1l[(size_t)D_DIM*HS_DIM];
__device__ __align__(16) __nv_bfloat16 g_Ws3h[(size_t)D_DIM*HS_DIM], g_Ws3l[(size_t)D_DIM*HS_DIM];
__device__ __align__(16) __nv_bfloat16 g_Ws2h[(size_t)HS_DIM*D_DIM], g_Ws2l[(size_t)HS_DIM*D_DIM];

// ---------------- helpers ----------------
__device__ __forceinline__ uint32_t smem_u32(const void* p) {
    return (uint32_t)__cvta_generic_to_shared(p);
}
__device__ __forceinline__ void cpa16(uint32_t dst, const void* src) {
    asm volatile("cp.async.cg.shared.global [%0], [%1], 16;" :: "r"(dst), "l"(src));
}
__device__ __forceinline__ void cpa16z(uint32_t dst, const void* src, bool valid) {
    int sz = valid ? 16 : 0;
    asm volatile("cp.async.cg.shared.global [%0], [%1], 16, %2;" :: "r"(dst), "l"(src), "r"(sz));
}
__device__ __forceinline__ void cpa_commit() { asm volatile("cp.async.commit_group;"); }
__device__ __forceinline__ void cpa_wait_all() { asm volatile("cp.async.wait_group 0;"); }
__device__ __forceinline__ void ldsm_x4(uint32_t* r, uint32_t a) {
    asm volatile("ldmatrix.sync.aligned.m8n8.x4.shared.b16 {%0,%1,%2,%3}, [%4];"
        : "=r"(r[0]), "=r"(r[1]), "=r"(r[2]), "=r"(r[3]) : "r"(a));
}
__device__ __forceinline__ void ldsm_x4_t(uint32_t* r, uint32_t a) {
    asm volatile("ldmatrix.sync.aligned.m8n8.x4.trans.shared.b16 {%0,%1,%2,%3}, [%4];"
        : "=r"(r[0]), "=r"(r[1]), "=r"(r[2]), "=r"(r[3]) : "r"(a));
}
__device__ __forceinline__ void mma16816(float* c, const uint32_t* a, const uint32_t* b) {
    asm volatile(
        "mma.sync.aligned.m16n8k16.row.col.f32.bf16.bf16.f32 "
        "{%0,%1,%2,%3}, {%4,%5,%6,%7}, {%8,%9}, {%0,%1,%2,%3};"
        : "+f"(c[0]), "+f"(c[1]), "+f"(c[2]), "+f"(c[3])
        : "r"(a[0]), "r"(a[1]), "r"(a[2]), "r"(a[3]), "r"(b[0]), "r"(b[1]));
}
__device__ __forceinline__ void split_bf16(float x, uint16_t& h, uint16_t& l) {
    __nv_bfloat16 hb = __float2bfloat16(x);
    float r = x - __bfloat162float(hb);
    __nv_bfloat16 lb = __float2bfloat16(r);
    h = __bfloat16_as_ushort(hb);
    l = __bfloat16_as_ushort(lb);
}
__device__ __forceinline__ void pack4(float4 v, uint2& hp, uint2& lp) {
    uint16_t hx,lx,hy,ly,hz,lz,hw,lw;
    split_bf16(v.x,hx,lx); split_bf16(v.y,hy,ly);
    split_bf16(v.z,hz,lz); split_bf16(v.w,hw,lw);
    hp = make_uint2((uint32_t)hx | ((uint32_t)hy<<16), (uint32_t)hz | ((uint32_t)hw<<16));
    lp = make_uint2((uint32_t)lx | ((uint32_t)ly<<16), (uint32_t)lz | ((uint32_t)lw<<16));
}

// ---------------- split: fp32 -> (hi,lo) bf16 ----------------
__global__ __launch_bounds__(256)
void split_kernel(const float4* __restrict__ src, uint2* __restrict__ h,
                  uint2* __restrict__ l, int n4)
{
    for (int i = blockIdx.x*blockDim.x + threadIdx.x; i < n4; i += gridDim.x*blockDim.x) {
        uint2 hp, lp; pack4(src[i], hp, lp);
        h[i] = hp; l[i] = lp;
    }
}

// ---------------- gating ----------------
__global__ __launch_bounds__(256)
void gate_kernel(const float* __restrict__ X, const float* __restrict__ Wg)
{
    int warp = (blockIdx.x*blockDim.x + threadIdx.x) >> 5;
    int lane = threadIdx.x & 31;
    if (warp >= T_TOK) return;
    const float* xr = X + (size_t)warp * D_DIM;
    float xv[32];
    #pragma unroll
    for (int i = 0; i < 32; i++) xv[i] = xr[lane + 32*i];

    float mylogit = 0.f;
    #pragma unroll 1
    for (int e = 0; e < E_NUM; e++) {
        float d = 0.f;
        #pragma unroll
        for (int i = 0; i < 32; i++)
            d += xv[i] * Wg[(size_t)(lane + 32*i)*E_NUM + e];
        #pragma unroll
        for (int off = 16; off; off >>= 1) d += __shfl_xor_sync(0xffffffffu, d, off);
        if (lane == e) mylogit = d;
    }
    float m = mylogit;
    #pragma unroll
    for (int off = 16; off; off >>= 1) m = fmaxf(m, __shfl_xor_sync(0xffffffffu, m, off));
    float p = expf(mylogit - m);
    float s = p;
    #pragma unroll
    for (int off = 16; off; off >>= 1) s += __shfl_xor_sync(0xffffffffu, s, off);
    float prob = p / s;

    for (int k = 0; k < TOPK; k++) {
        float v = prob; int idx = lane;
        #pragma unroll
        for (int off = 16; off; off >>= 1) {
            float ov = __shfl_xor_sync(0xffffffffu, v, off);
            int   oi = __shfl_xor_sync(0xffffffffu, idx, off);
            if (ov > v || (ov == v && oi < idx)) { v = ov; idx = oi; }
        }
        if (lane == 0) {
            g_pair_e[warp*TOPK + k] = idx;
            g_pair_w[warp*TOPK + k] = v;
        }
        if (lane == idx) prob = -1.f;
    }
}

// ---------------- dispatch ----------------
__global__ __launch_bounds__(256)
void dispatch_kernel()
{
    int e = blockIdx.x;
    int tid = threadIdx.x;
    int lane = tid & 31, wid = tid >> 5;
    __shared__ int wtot[8];
    __shared__ int s_run;
    if (tid == 0) s_run = 0;
    __syncthreads();

    for (int base = 0; base < P_PAIRS; base += 256) {
        int p = base + tid;
        int flag = (g_pair_e[p] == e) ? 1 : 0;
        unsigned b = __ballot_sync(0xffffffffu, flag);
        int woff = __popc(b & ((1u << lane) - 1u));
        if (lane == 0) wtot[wid] = __popc(b);
        __syncthreads();
        int excl = 0, tot = 0;
        #pragma unroll
        for (int w = 0; w < 8; w++) { if (w < wid) excl += wtot[w]; tot += wtot[w]; }
        int pos = s_run + excl + woff;
        if (flag && pos < CAP) {
            g_slot_tok[e*CAP + pos] = p >> 2;
            g_slot_w  [e*CAP + pos] = g_pair_w[p];
        }
        __syncthreads();
        if (tid == 0) s_run += tot;
        __syncthreads();
    }
    if (tid == 0) g_count[e] = min(s_run, CAP);
}

// ---------------- fused up-proj: H = silu(X@W1)*(X@W3), bf16x3, cp.async 2-stage ---
__global__ __launch_bounds__(256, 2)
void up_mma(int NN, int expert_mode)
{
    extern __shared__ __nv_bfloat16 sm[];
    // halves offsets
    auto pAh  = [&](int s){ return sm + (size_t)s*SA; };
    auto pAl  = [&](int s){ return sm + (size_t)(2+s)*SA; };
    auto pB1h = [&](int s){ return sm + (size_t)4*SA + (size_t)s*SB; };
    auto pB1l = [&](int s){ return sm + (size_t)4*SA + (size_t)(2+s)*SB; };
    auto pB3h = [&](int s){ return sm + (size_t)4*SA + (size_t)(4+s)*SB; };
    auto pB3l = [&](int s){ return sm + (size_t)4*SA + (size_t)(6+s)*SB; };

    int e = blockIdx.z;
    int M_eff; const int* rows = nullptr;
    const __nv_bfloat16 *W1h, *W1l, *W3h, *W3l;
    __nv_bfloat16 *Hhi, *Hlo;
    if (expert_mode) {
        M_eff = g_count[e];
        rows  = g_slot_tok + e*CAP;
        size_t wo = (size_t)e*D_DIM*H_DIM;
        W1h = g_W1h + wo; W1l = g_W1l + wo;
        W3h = g_W3h + wo; W3l = g_W3l + wo;
        Hhi = g_hexp_hi + (size_t)e*CAP*NN;
        Hlo = g_hexp_lo + (size_t)e*CAP*NN;
    } else {
        M_eff = T_TOK;
        W1h = g_Ws1h; W1l = g_Ws1l; W3h = g_Ws3h; W3l = g_Ws3l;
        Hhi = g_hsh_hi; Hlo = g_hsh_lo;
    }
    int mbase = blockIdx.x * BM;
    if (mbase >= M_eff) return;
    int nbase = blockIdx.y * BN;

    int tid = threadIdx.x, lane = tid & 31, wid = tid >> 5;
    int wm = wid >> 1, wn = wid & 1;

    // A staging: thread handles rows ar0 and ar0+64, 16B chunk aq
    int ar0 = tid >> 2;
    int aq  = (tid & 3) * 8;
    bool av[2]; const __nv_bfloat16 *XhP[2], *XlP[2];
    #pragma unroll
    for (int h = 0; h < 2; h++) {
        int r = mbase + ar0 + h*64;
        av[h] = r < M_eff;
        int grow = av[h] ? (rows ? rows[ar0 + h*64 + mbase - mbase + (rows ? 0 : 0)] : r) : 0;
        // note: rows is indexed by slot (mbase+ar0+h*64)
        if (av[h] && rows) grow = rows[mbase + ar0 + h*64];
        XhP[h] = g_Xh + (size_t)grow*D_DIM + aq;
        XlP[h] = g_Xl + (size_t)grow*D_DIM + aq;
    }
    // B staging: row br, chunk bq
    int br = tid >> 3, bq = (tid & 7) * 8;
    const __nv_bfloat16* W1hP = W1h + (size_t)br*NN + nbase + bq;
    const __nv_bfloat16* W1lP = W1l + (size_t)br*NN + nbase + bq;
    const __nv_bfloat16* W3hP = W3h + (size_t)br*NN + nbase + bq;
    const __nv_bfloat16* W3lP = W3l + (size_t)br*NN + nbase + bq;

    auto load_stage = [&](int s, int kt) {
        #pragma unroll
        for (int h = 0; h < 2; h++) {
            int row = ar0 + h*64;
            cpa16z(smem_u32(pAh(s) + row*ASTR + aq), XhP[h] + kt, av[h]);
            cpa16z(smem_u32(pAl(s) + row*ASTR + aq), XlP[h] + kt, av[h]);
        }
        size_t ko = (size_t)kt*NN;
        cpa16(smem_u32(pB1h(s) + br*BSTR + bq), W1hP + ko);
        cpa16(smem_u32(pB1l(s) + br*BSTR + bq), W1lP + ko);
        cpa16(smem_u32(pB3h(s) + br*BSTR + bq), W3hP + ko);
        cpa16(smem_u32(pB3l(s) + br*BSTR + bq), W3lP + ko);
        cpa_commit();
    };

    float c1[2][4][4] = {}, c3[2][4][4] = {};
    const int NT = D_DIM / BK;

    load_stage(0, 0);
    int cur = 0;
    for (int t = 0; t < NT; t++) {
        cpa_wait_all();
        __syncthreads();
        if (t + 1 < NT) load_stage(cur ^ 1, (t + 1) * BK);

        #pragma unroll
        for (int ks = 0; ks < 2; ks++) {
            int k0 = ks * 16;
            uint32_t ah[2][4], al[2][4];
            #pragma unroll
            for (int mt = 0; mt < 2; mt++) {
                int r = wm*32 + mt*16 + (lane & 15);
                int c = k0 + (lane >> 4) * 8;
                ldsm_x4(ah[mt], smem_u32(pAh(cur) + r*ASTR + c));
                ldsm_x4(al[mt], smem_u32(pAl(cur) + r*ASTR + c));
            }
            #pragma unroll
            for (int h = 0; h < 2; h++) {
                int rr = k0 + (lane & 7) + ((lane >> 3) & 1) * 8;
                int cc = wn*32 + h*16 + (lane >> 4) * 8;
                uint32_t b1hf[2][2], b1lf[2][2], b3hf[2][2], b3lf[2][2];
                uint32_t t4[4];
                ldsm_x4_t(t4, smem_u32(pB1h(cur) + rr*BSTR + cc));
                b1hf[0][0]=t4[0]; b1hf[0][1]=t4[1]; b1hf[1][0]=t4[2]; b1hf[1][1]=t4[3];
                ldsm_x4_t(t4, smem_u32(pB1l(cur) + rr*BSTR + cc));
                b1lf[0][0]=t4[0]; b1lf[0][1]=t4[1]; b1lf[1][0]=t4[2]; b1lf[1][1]=t4[3];
                ldsm_x4_t(t4, smem_u32(pB3h(cur) + rr*BSTR + cc));
                b3hf[0][0]=t4[0]; b3hf[0][1]=t4[1]; b3hf[1][0]=t4[2]; b3hf[1][1]=t4[3];
                ldsm_x4_t(t4, smem_u32(pB3l(cur) + rr*BSTR + cc));
                b3lf[0][0]=t4[0]; b3lf[0][1]=t4[1]; b3lf[1][0]=t4[2]; b3lf[1][1]=t4[3];
                #pragma unroll
                for (int mt = 0; mt < 2; mt++)
                    #pragma unroll
                    for (int j = 0; j < 2; j++) {
                        int nt = h*2 + j;
                        mma16816(c1[mt][nt], ah[mt], b1hf[j]);
                        mma16816(c1[mt][nt], ah[mt], b1lf[j]);
                        mma16816(c1[mt][nt], al[mt], b1hf[j]);
                        mma16816(c3[mt][nt], ah[mt], b3hf[j]);
                        mma16816(c3[mt][nt], ah[mt], b3lf[j]);
                        mma16816(c3[mt][nt], al[mt], b3hf[j]);
                    }
            }
        }
        __syncthreads();
        cur ^= 1;
    }

    int r0 = lane >> 2, cb = (lane & 3) * 2;
    #pragma unroll
    for (int mt = 0; mt < 2; mt++)
        #pragma unroll
        for (int nt = 0; nt < 4; nt++) {
            int n = nbase + wn*32 + nt*8 + cb;
            #pragma unroll
            for (int p = 0; p < 2; p++) {
                int m = mbase + wm*32 + mt*16 + r0 + p*8;
                if (m < M_eff) {
                    float g0 = c1[mt][nt][2*p+0], g1 = c1[mt][nt][2*p+1];
                    float v0 = g0 / (1.f + expf(-g0)) * c3[mt][nt][2*p+0];
                    float v1 = g1 / (1.f + expf(-g1)) * c3[mt][nt][2*p+1];
                    uint16_t h0,l0,h1,l1;
                    split_bf16(v0,h0,l0); split_bf16(v1,h1,l1);
                    *(uint32_t*)&Hhi[(size_t)m*NN + n] = (uint32_t)h0 | ((uint32_t)h1<<16);
                    *(uint32_t*)&Hlo[(size_t)m*NN + n] = (uint32_t)l0 | ((uint32_t)l1<<16);
                }
            }
        }
}

// ---------------- down-proj: out (+)= w*(H@W2), bf16x3, cp.async 2-stage ----------
__global__ __launch_bounds__(256, 2)
void down_mma(int KK, int expert_mode, float* __restrict__ out)
{
    extern __shared__ __nv_bfloat16 sm[];
    auto pAh = [&](int s){ return sm + (size_t)s*SA; };
    auto pAl = [&](int s){ return sm + (size_t)(2+s)*SA; };
    auto pBh = [&](int s){ return sm + (size_t)4*SA + (size_t)s*SB; };
    auto pBl = [&](int s){ return sm + (size_t)4*SA + (size_t)(2+s)*SB; };

    int e = blockIdx.z;
    int M_eff; const int* rows = nullptr; const float* wv = nullptr;
    const __nv_bfloat16 *W2h, *W2l, *HhiP, *HloP;
    if (expert_mode) {
        M_eff = g_count[e];
        rows  = g_slot_tok + e*CAP;
        wv    = g_slot_w  + e*CAP;
        size_t wo = (size_t)e*H_DIM*D_DIM;
        W2h = g_W2h + wo; W2l = g_W2l + wo;
        HhiP = g_hexp_hi + (size_t)e*CAP*KK;
        HloP = g_hexp_lo + (size_t)e*CAP*KK;
    } else {
        M_eff = T_TOK; W2h = g_Ws2h; W2l = g_Ws2l;
        HhiP = g_hsh_hi; HloP = g_hsh_lo;
    }
    int mbase = blockIdx.x * BM;
    if (mbase >= M_eff) return;
    int nbase = blockIdx.y * BN;

    int tid = threadIdx.x, lane = tid & 31, wid = tid >> 5;
    int wm = wid >> 1, wn = wid & 1;

    int ar0 = tid >> 2;
    int aq  = (tid & 3) * 8;
    bool av[2]; const __nv_bfloat16 *AhP[2], *AlP[2];
    #pragma unroll
    for (int h = 0; h < 2; h++) {
        int r = mbase + ar0 + h*64;
        av[h] = r < M_eff;
        int rr = av[h] ? r : mbase;
        AhP[h] = HhiP + (size_t)rr*KK + aq;
        AlP[h] = HloP + (size_t)rr*KK + aq;
    }
    int br = tid >> 3, bq = (tid & 7) * 8;
    const __nv_bfloat16* BhP = W2h + (size_t)br*D_DIM + nbase + bq;
    const __nv_bfloat16* BlP = W2l + (size_t)br*D_DIM + nbase + bq;

    auto load_stage = [&](int s, int kt) {
        #pragma unroll
        for (int h = 0; h < 2; h++) {
            int row = ar0 + h*64;
            cpa16z(smem_u32(pAh(s) + row*ASTR + aq), AhP[h] + kt, av[h]);
            cpa16z(smem_u32(pAl(s) + row*ASTR + aq), AlP[h] + kt, av[h]);
        }
        size_t ko = (size_t)kt*D_DIM;
        cpa16(smem_u32(pBh(s) + br*BSTR + bq), BhP + ko);
        cpa16(smem_u32(pBl(s) + br*BSTR + bq), BlP + ko);
        cpa_commit();
    };

    float c[2][4][4] = {};
    const int NT = KK / BK;

    load_stage(0, 0);
    int cur = 0;
    for (int t = 0; t < NT; t++) {
        cpa_wait_all();
        __syncthreads();
        if (t + 1 < NT) load_stage(cur ^ 1, (t + 1) * BK);

        #pragma unroll
        for (int ks = 0; ks < 2; ks++) {
            int k0 = ks * 16;
            uint32_t ah[2][4], al[2][4];
            #pragma unroll
            for (int mt = 0; mt < 2; mt++) {
                int r = wm*32 + mt*16 + (lane & 15);
                int cc = k0 + (lane >> 4) * 8;
                ldsm_x4(ah[mt], smem_u32(pAh(cur) + r*ASTR + cc));
                ldsm_x4(al[mt], smem_u32(pAl(cur) + r*ASTR + cc));
            }
            #pragma unroll
            for (int h = 0; h < 2; h++) {
                int rr = k0 + (lane & 7) + ((lane >> 3) & 1) * 8;
                int cc = wn*32 + h*16 + (lane >> 4) * 8;
                uint32_t bhf[2][2], blf[2][2];
                uint32_t t4[4];
                ldsm_x4_t(t4, smem_u32(pBh(cur) + rr*BSTR + cc));
                bhf[0][0]=t4[0]; bhf[0][1]=t4[1]; bhf[1][0]=t4[2]; bhf[1][1]=t4[3];
                ldsm_x4_t(t4, smem_u32(pBl(cur) + rr*BSTR + cc));
                blf[0][0]=t4[0]; blf[0][1]=t4[1]; blf[1][0]=t4[2]; blf[1][1]=t4[3];
                #pragma unroll
                for (int mt = 0; mt < 2; mt++)
                    #pragma unroll
                    for (int j = 0; j < 2; j++) {
                        int nt = h*2 + j;
                        mma16816(c[mt][nt], ah[mt], bhf[j]);
                        mma16816(c[mt][nt], ah[mt], blf[j]);
                        mma16816(c[mt][nt], al[mt], bhf[j]);
                    }
            }
        }
        __syncthreads();
        cur ^= 1;
    }

    int r0 = lane >> 2, cb = (lane & 3) * 2;
    #pragma unroll
    for (int mt = 0; mt < 2; mt++)
        #pragma unroll
        for (int nt = 0; nt < 4; nt++) {
            int n = nbase + wn*32 + nt*8 + cb;
            #pragma unroll
            for (int p = 0; p < 2; p++) {
                int m = mbase + wm*32 + mt*16 + r0 + p*8;
                if (m < M_eff) {
                    float v0 = c[mt][nt][2*p+0], v1 = c[mt][nt][2*p+1];
                    if (expert_mode) {
                        int tok = rows[m];
                        float w = wv[m];
                        float* orow = out + (size_t)tok*D_DIM + n;
                        atomicAdd(&orow[0], v0 * w);
                        atomicAdd(&orow[1], v1 * w);
                    } else {
                        *(float2*)(out + (size_t)m*D_DIM + n) = make_float2(v0, v1);
                    }
                }
            }
        }
}

// ---------------- host launcher ----------------
static void split_launch(const void* src, const void* hsym, const void* lsym, size_t n) {
    // hsym/lsym are device pointers already resolved
    int n4 = (int)(n / 4);
    int grid = 2048;
    split_kernel<<<grid, 256>>>((const float4*)src, (uint2*)hsym, (uint2*)lsym, n4);
}

extern "C" void kernel_launch(void* const* d_in, const int* in_sizes, int n_in,
                              void* d_out, int out_size)
{
    const float* x   = (const float*)d_in[0];
    const float* Wg  = (const float*)d_in[1];
    const float* W1  = (const float*)d_in[2];
    const float* W2  = (const float*)d_in[3];
    const float* W3  = (const float*)d_in[4];
    const float* Ws1 = (const float*)d_in[5];
    const float* Ws2 = (const float*)d_in[6];
    const float* Ws3 = (const float*)d_in[7];
    float* out = (float*)d_out;

    cudaFuncSetAttribute(up_mma,   cudaFuncAttributeMaxDynamicSharedMemorySize, UP_SMEM_BYTES);
    cudaFuncSetAttribute(down_mma, cudaFuncAttributeMaxDynamicSharedMemorySize, DOWN_SMEM_BYTES);

    void *xh, *xl, *w1h, *w1l, *w3h, *w3l, *w2h, *w2l;
    void *ws1h, *ws1l, *ws3h, *ws3l, *ws2h, *ws2l;
    cudaGetSymbolAddress(&xh,  g_Xh);  cudaGetSymbolAddress(&xl,  g_Xl);
    cudaGetSymbolAddress(&w1h, g_W1h); cudaGetSymbolAddress(&w1l, g_W1l);
    cudaGetSymbolAddress(&w3h, g_W3h); cudaGetSymbolAddress(&w3l, g_W3l);
    cudaGetSymbolAddress(&w2h, g_W2h); cudaGetSymbolAddress(&w2l, g_W2l);
    cudaGetSymbolAddress(&ws1h, g_Ws1h); cudaGetSymbolAddress(&ws1l, g_Ws1l);
    cudaGetSymbolAddress(&ws3h, g_Ws3h); cudaGetSymbolAddress(&ws3l, g_Ws3l);
    cudaGetSymbolAddress(&ws2h, g_Ws2h); cudaGetSymbolAddress(&ws2l, g_Ws2l);

    gate_kernel<<<T_TOK/8, 256>>>(x, Wg);
    dispatch_kernel<<<E_NUM, 256>>>();

    split_launch(x,   xh,  xl,  (size_t)T_TOK*D_DIM);
    split_launch(W1,  w1h, w1l, (size_t)E_NUM*D_DIM*H_DIM);
    split_launch(W3,  w3h, w3l, (size_t)E_NUM*D_DIM*H_DIM);
    split_launch(W2,  w2h, w2l, (size_t)E_NUM*H_DIM*D_DIM);
    split_launch(Ws1, ws1h, ws1l, (size_t)D_DIM*HS_DIM);
    split_launch(Ws3, ws3h, ws3l, (size_t)D_DIM*HS_DIM);
    split_launch(Ws2, ws2h, ws2l, (size_t)HS_DIM*D_DIM);

    // shared expert (dense) — down stores initialize every out element
    up_mma  <<<dim3(T_TOK/BM, HS_DIM/BN, 1), 256, UP_SMEM_BYTES>>>(HS_DIM, 0);
    down_mma<<<dim3(T_TOK/BM, D_DIM/BN, 1), 256, DOWN_SMEM_BYTES>>>(HS_DIM, 0, out);

    // routed experts
    up_mma  <<<dim3(CAP/BM, H_DIM/BN, E_NUM), 256, UP_SMEM_BYTES>>>(H_DIM, 1);
    down_mma<<<dim3(CAP/BM, D_DIM/BN, E_NUM), 256, DOWN_SMEM_BYTES>>>(H_DIM, 1, out);
}

// round 5
// speedup vs baseline: 2.0438x; 1.0940x over previous
#include <cuda_runtime.h>
#include <cuda_bf16.h>
#include <math.h>
#include <stdint.h>

#define T_TOK   4096
#define D_DIM   1024
#define H_DIM   512
#define HS_DIM  1024
#define E_NUM   32
#define TOPK    4
#define P_PAIRS (T_TOK*TOPK)
#define CAP     2048

#define BM 128
#define BK 32
#define STAGE_BYTES 32768
#define N_STAGE 3
#define DYN_SMEM (N_STAGE*STAGE_BYTES)

// ---------------- scratch ----------------
__device__ int   g_pair_e[P_PAIRS];
__device__ float g_pair_w[P_PAIRS];
__device__ int   g_slot_tok[E_NUM*CAP];
__device__ float g_slot_w[E_NUM*CAP];
__device__ int   g_count[E_NUM];
__device__ __align__(16) __nv_bfloat16 g_hexp_hi[(size_t)E_NUM*CAP*H_DIM];
__device__ __align__(16) __nv_bfloat16 g_hexp_lo[(size_t)E_NUM*CAP*H_DIM];
__device__ __align__(16) __nv_bfloat16 g_hsh_hi[(size_t)T_TOK*HS_DIM];
__device__ __align__(16) __nv_bfloat16 g_hsh_lo[(size_t)T_TOK*HS_DIM];
// pre-split operands (all stay in native K-major layout)
__device__ __align__(16) __nv_bfloat16 g_Xh[(size_t)T_TOK*D_DIM],  g_Xl[(size_t)T_TOK*D_DIM];
__device__ __align__(16) __nv_bfloat16 g_W1h[(size_t)E_NUM*D_DIM*H_DIM], g_W1l[(size_t)E_NUM*D_DIM*H_DIM];
__device__ __align__(16) __nv_bfloat16 g_W3h[(size_t)E_NUM*D_DIM*H_DIM], g_W3l[(size_t)E_NUM*D_DIM*H_DIM];
__device__ __align__(16) __nv_bfloat16 g_W2h[(size_t)E_NUM*H_DIM*D_DIM], g_W2l[(size_t)E_NUM*H_DIM*D_DIM];
__device__ __align__(16) __nv_bfloat16 g_Ws1h[(size_t)D_DIM*HS_DIM], g_Ws1l[(size_t)D_DIM*HS_DIM];
__device__ __align__(16) __nv_bfloat16 g_Ws3h[(size_t)D_DIM*HS_DIM], g_Ws3l[(size_t)D_DIM*HS_DIM];
__device__ __align__(16) __nv_bfloat16 g_Ws2h[(size_t)HS_DIM*D_DIM], g_Ws2l[(size_t)HS_DIM*D_DIM];

// ---------------- helpers ----------------
__device__ __forceinline__ uint32_t smem_u32(const void* p) {
    return (uint32_t)__cvta_generic_to_shared(p);
}
__device__ __forceinline__ void cpa16(uint32_t dst, const void* src) {
    asm volatile("cp.async.cg.shared.global [%0], [%1], 16;" :: "r"(dst), "l"(src));
}
__device__ __forceinline__ void cpa16z(uint32_t dst, const void* src, bool valid) {
    int sz = valid ? 16 : 0;
    asm volatile("cp.async.cg.shared.global [%0], [%1], 16, %2;" :: "r"(dst), "l"(src), "r"(sz));
}
__device__ __forceinline__ void cpa_commit() { asm volatile("cp.async.commit_group;"); }
__device__ __forceinline__ void cpa_wait0()  { asm volatile("cp.async.wait_group 0;"); }
__device__ __forceinline__ void cpa_wait1()  { asm volatile("cp.async.wait_group 1;"); }
__device__ __forceinline__ void ldsm_x4(uint32_t* r, uint32_t a) {
    asm volatile("ldmatrix.sync.aligned.m8n8.x4.shared.b16 {%0,%1,%2,%3}, [%4];"
        : "=r"(r[0]), "=r"(r[1]), "=r"(r[2]), "=r"(r[3]) : "r"(a));
}
__device__ __forceinline__ void ldsm_x4_t(uint32_t* r, uint32_t a) {
    asm volatile("ldmatrix.sync.aligned.m8n8.x4.trans.shared.b16 {%0,%1,%2,%3}, [%4];"
        : "=r"(r[0]), "=r"(r[1]), "=r"(r[2]), "=r"(r[3]) : "r"(a));
}
__device__ __forceinline__ void mma16816(float* c, const uint32_t* a, const uint32_t* b) {
    asm volatile(
        "mma.sync.aligned.m16n8k16.row.col.f32.bf16.bf16.f32 "
        "{%0,%1,%2,%3}, {%4,%5,%6,%7}, {%8,%9}, {%0,%1,%2,%3};"
        : "+f"(c[0]), "+f"(c[1]), "+f"(c[2]), "+f"(c[3])
        : "r"(a[0]), "r"(a[1]), "r"(a[2]), "r"(a[3]), "r"(b[0]), "r"(b[1]));
}
__device__ __forceinline__ void split_bf16(float x, uint16_t& h, uint16_t& l) {
    __nv_bfloat16 hb = __float2bfloat16(x);
    float r = x - __bfloat162float(hb);
    __nv_bfloat16 lb = __float2bfloat16(r);
    h = __bfloat16_as_ushort(hb);
    l = __bfloat16_as_ushort(lb);
}
__device__ __forceinline__ void pack4(float4 v, uint2& hp, uint2& lp) {
    uint16_t hx,lx,hy,ly,hz,lz,hw,lw;
    split_bf16(v.x,hx,lx); split_bf16(v.y,hy,ly);
    split_bf16(v.z,hz,lz); split_bf16(v.w,hw,lw);
    hp = make_uint2((uint32_t)hx | ((uint32_t)hy<<16), (uint32_t)hz | ((uint32_t)hw<<16));
    lp = make_uint2((uint32_t)lx | ((uint32_t)ly<<16), (uint32_t)lz | ((uint32_t)lw<<16));
}
// swizzled offsets (bytes).  A tiles: 64B rows (BK=32 halves).  B tiles: RB-byte rows.
__device__ __forceinline__ uint32_t a_off(int r, int s) {          // s = 16B chunk 0..3
    return (uint32_t)r*64u + (uint32_t)((s ^ ((r>>1)&3)) << 4);
}
__device__ __forceinline__ uint32_t b_off(int r, int s, int RB) {  // s = 16B chunk
    return (uint32_t)r*(uint32_t)RB + (uint32_t)((s ^ (r&7)) << 4);
}

// ---------------- split: fp32 -> (hi,lo) bf16 ----------------
__global__ __launch_bounds__(256)
void split_kernel(const float4* __restrict__ src, uint2* __restrict__ h,
                  uint2* __restrict__ l, int n4)
{
    for (int i = blockIdx.x*blockDim.x + threadIdx.x; i < n4; i += gridDim.x*blockDim.x) {
        uint2 hp, lp; pack4(src[i], hp, lp);
        h[i] = hp; l[i] = lp;
    }
}

// ---------------- gating ----------------
__global__ __launch_bounds__(256)
void gate_kernel(const float* __restrict__ X, const float* __restrict__ Wg)
{
    int warp = (blockIdx.x*blockDim.x + threadIdx.x) >> 5;
    int lane = threadIdx.x & 31;
    if (warp >= T_TOK) return;
    const float* xr = X + (size_t)warp * D_DIM;
    float xv[32];
    #pragma unroll
    for (int i = 0; i < 32; i++) xv[i] = xr[lane + 32*i];

    float mylogit = 0.f;
    #pragma unroll 1
    for (int e = 0; e < E_NUM; e++) {
        float d = 0.f;
        #pragma unroll
        for (int i = 0; i < 32; i++)
            d += xv[i] * Wg[(size_t)(lane + 32*i)*E_NUM + e];
        #pragma unroll
        for (int off = 16; off; off >>= 1) d += __shfl_xor_sync(0xffffffffu, d, off);
        if (lane == e) mylogit = d;
    }
    float m = mylogit;
    #pragma unroll
    for (int off = 16; off; off >>= 1) m = fmaxf(m, __shfl_xor_sync(0xffffffffu, m, off));
    float p = expf(mylogit - m);
    float s = p;
    #pragma unroll
    for (int off = 16; off; off >>= 1) s += __shfl_xor_sync(0xffffffffu, s, off);
    float prob = p / s;

    for (int k = 0; k < TOPK; k++) {
        float v = prob; int idx = lane;
        #pragma unroll
        for (int off = 16; off; off >>= 1) {
            float ov = __shfl_xor_sync(0xffffffffu, v, off);
            int   oi = __shfl_xor_sync(0xffffffffu, idx, off);
            if (ov > v || (ov == v && oi < idx)) { v = ov; idx = oi; }
        }
        if (lane == 0) {
            g_pair_e[warp*TOPK + k] = idx;
            g_pair_w[warp*TOPK + k] = v;
        }
        if (lane == idx) prob = -1.f;
    }
}

// ---------------- dispatch ----------------
__global__ __launch_bounds__(256)
void dispatch_kernel()
{
    int e = blockIdx.x;
    int tid = threadIdx.x;
    int lane = tid & 31, wid = tid >> 5;
    __shared__ int wtot[8];
    __shared__ int s_run;
    if (tid == 0) s_run = 0;
    __syncthreads();

    for (int base = 0; base < P_PAIRS; base += 256) {
        int p = base + tid;
        int flag = (g_pair_e[p] == e) ? 1 : 0;
        unsigned b = __ballot_sync(0xffffffffu, flag);
        int woff = __popc(b & ((1u << lane) - 1u));
        if (lane == 0) wtot[wid] = __popc(b);
        __syncthreads();
        int excl = 0, tot = 0;
        #pragma unroll
        for (int w = 0; w < 8; w++) { if (w < wid) excl += wtot[w]; tot += wtot[w]; }
        int pos = s_run + excl + woff;
        if (flag && pos < CAP) {
            g_slot_tok[e*CAP + pos] = p >> 2;
            g_slot_w  [e*CAP + pos] = g_pair_w[p];
        }
        __syncthreads();
        if (tid == 0) s_run += tot;
        __syncthreads();
    }
    if (tid == 0) g_count[e] = min(s_run, CAP);
}

// =====================================================================
// up: H = silu(X@W1) * (X@W3)  — mma.sync bf16 3-pass, 3-stage cp.async
// block 128x64, warps 2Mx4N, warp tile 64x16 (x2 outputs)
// stage: Ah 0 Al 8192 B1h 16384 B1l 20480 B3h 24576 B3l 28672  (RB_B=128)
// =====================================================================
__global__ __launch_bounds__(256, 2)
void up_mma(int NN, int expert_mode)
{
    extern __shared__ char sm[];
    uint32_t sbase = smem_u32(sm);

    int e = blockIdx.z;
    int M_eff; const int* rows = nullptr;
    const __nv_bfloat16 *B1h_g, *B1l_g, *B3h_g, *B3l_g;
    __nv_bfloat16 *Hhi, *Hlo;
    if (expert_mode) {
        M_eff = g_count[e];
        rows  = g_slot_tok + e*CAP;
        size_t wo = (size_t)e*D_DIM*H_DIM;
        B1h_g = g_W1h + wo; B1l_g = g_W1l + wo;
        B3h_g = g_W3h + wo; B3l_g = g_W3l + wo;
        Hhi = g_hexp_hi + (size_t)e*CAP*NN;
        Hlo = g_hexp_lo + (size_t)e*CAP*NN;
    } else {
        M_eff = T_TOK;
        B1h_g = g_Ws1h; B1l_g = g_Ws1l; B3h_g = g_Ws3h; B3l_g = g_Ws3l;
        Hhi = g_hsh_hi; Hlo = g_hsh_lo;
    }
    int mbase = blockIdx.x * BM;
    if (mbase >= M_eff) return;
    int nbase = blockIdx.y * 64;
    const int KK = D_DIM;
    const int NT = KK / BK;

    int tid = threadIdx.x, lane = tid & 31, wid = tid >> 5;
    int wm = wid >> 2, wn = wid & 3;

    // A staging: thread -> rows (tid>>2) and (tid>>2)+64, chunk s = tid&3
    int ar0 = tid >> 2, as = tid & 3;
    bool avA[2]; const __nv_bfloat16 *XhP[2], *XlP[2];
    #pragma unroll
    for (int h = 0; h < 2; h++) {
        int slot = mbase + ar0 + h*64;
        avA[h] = slot < M_eff;
        int tok = avA[h] ? (rows ? rows[slot] : slot) : 0;
        XhP[h] = g_Xh + (size_t)tok*KK + as*8;
        XlP[h] = g_Xl + (size_t)tok*KK + as*8;
    }
    // B staging: thread -> row tid>>3, chunk tid&7 (one 16B chunk per matrix)
    int brow = tid >> 3, bs = tid & 7;

    auto load_stage = [&](int s, int kt) {
        uint32_t st = sbase + (uint32_t)s*STAGE_BYTES;
        #pragma unroll
        for (int h = 0; h < 2; h++) {
            uint32_t d = a_off(ar0 + h*64, as);
            cpa16z(st + d,        XhP[h] + kt, avA[h]);
            cpa16z(st + 8192 + d, XlP[h] + kt, avA[h]);
        }
        uint32_t d = b_off(brow, bs, 128);
        size_t src = (size_t)(kt + brow)*NN + nbase + bs*8;
        cpa16(st + 16384 + d, B1h_g + src);
        cpa16(st + 20480 + d, B1l_g + src);
        cpa16(st + 24576 + d, B3h_g + src);
        cpa16(st + 28672 + d, B3l_g + src);
        cpa_commit();
    };

    float c1[4][2][4] = {}, c3[4][2][4] = {};

    load_stage(0, 0);
    load_stage(1, BK);
    for (int t = 0; t < NT; t++) {
        int s = t % N_STAGE;
        if (t < NT - 1) cpa_wait1(); else cpa_wait0();
        __syncthreads();
        if (t + 2 < NT) load_stage((t + 2) % N_STAGE, (t + 2) * BK);

        uint32_t st = sbase + (uint32_t)s*STAGE_BYTES;
        #pragma unroll
        for (int ks = 0; ks < 2; ks++) {
            int k0 = ks * 16;
            // B frags: one trans ldsm per matrix per hi/lo
            int rr = k0 + (lane & 7) + ((lane >> 3) & 1) * 8;
            int cc = wn*16 + (lane >> 4) * 8;
            uint32_t boff = b_off(rr, cc >> 3, 128);
            uint32_t b1h[4], b1l[4], b3h[4], b3l[4];
            ldsm_x4_t(b1h, st + 16384 + boff);
            ldsm_x4_t(b1l, st + 20480 + boff);
            ldsm_x4_t(b3h, st + 24576 + boff);
            ldsm_x4_t(b3l, st + 28672 + boff);
            #pragma unroll
            for (int mt = 0; mt < 4; mt++) {
                int r = wm*64 + mt*16 + (lane & 15);
                int sA = (k0 >> 3) + (lane >> 4);
                uint32_t aoff = a_off(r, sA);
                uint32_t ah[4], al[4];
                ldsm_x4(ah, st + aoff);
                ldsm_x4(al, st + 8192 + aoff);
                #pragma unroll
                for (int nt = 0; nt < 2; nt++) {
                    mma16816(c1[mt][nt], ah, &b1h[nt*2]);
                    mma16816(c1[mt][nt], ah, &b1l[nt*2]);
                    mma16816(c1[mt][nt], al, &b1h[nt*2]);
                    mma16816(c3[mt][nt], ah, &b3h[nt*2]);
                    mma16816(c3[mt][nt], ah, &b3l[nt*2]);
                    mma16816(c3[mt][nt], al, &b3h[nt*2]);
                }
            }
        }
    }

    int r0 = lane >> 2, cb = (lane & 3) * 2;
    #pragma unroll
    for (int mt = 0; mt < 4; mt++)
        #pragma unroll
        for (int nt = 0; nt < 2; nt++) {
            int n = nbase + wn*16 + nt*8 + cb;
            #pragma unroll
            for (int p = 0; p < 2; p++) {
                int m = mbase + wm*64 + mt*16 + r0 + p*8;
                if (m < M_eff) {
                    float g0 = c1[mt][nt][2*p+0], g1 = c1[mt][nt][2*p+1];
                    float v0 = g0 / (1.f + expf(-g0)) * c3[mt][nt][2*p+0];
                    float v1 = g1 / (1.f + expf(-g1)) * c3[mt][nt][2*p+1];
                    uint16_t h0,l0,h1,l1;
                    split_bf16(v0,h0,l0); split_bf16(v1,h1,l1);
                    *(uint32_t*)&Hhi[(size_t)m*NN + n] = (uint32_t)h0 | ((uint32_t)h1<<16);
                    *(uint32_t*)&Hlo[(size_t)m*NN + n] = (uint32_t)l0 | ((uint32_t)l1<<16);
                }
            }
        }
}

// =====================================================================
// down: out (+)= w * (H@W2) — mma.sync bf16 3-pass, 3-stage cp.async
// block 128x128, warps 2Mx4N, warp tile 64x32
// stage: Ah 0 Al 8192 Bh 16384 Bl 24576  (RB_B=256)
// =====================================================================
__global__ __launch_bounds__(256, 2)
void down_mma(int KK, int expert_mode, float* __restrict__ out)
{
    extern __shared__ char sm[];
    uint32_t sbase = smem_u32(sm);

    int e = blockIdx.z;
    int M_eff; const int* rows = nullptr; const float* wv = nullptr;
    const __nv_bfloat16 *Ah_g, *Al_g, *Bh_g, *Bl_g;
    if (expert_mode) {
        M_eff = g_count[e];
        rows  = g_slot_tok + e*CAP;
        wv    = g_slot_w  + e*CAP;
        size_t wo = (size_t)e*H_DIM*D_DIM;
        Bh_g = g_W2h + wo; Bl_g = g_W2l + wo;
        Ah_g = g_hexp_hi + (size_t)e*CAP*KK;
        Al_g = g_hexp_lo + (size_t)e*CAP*KK;
    } else {
        M_eff = T_TOK;
        Bh_g = g_Ws2h; Bl_g = g_Ws2l;
        Ah_g = g_hsh_hi; Al_g = g_hsh_lo;
    }
    int mbase = blockIdx.x * BM;
    if (mbase >= M_eff) return;
    int nbase = blockIdx.y * 128;
    const int NT = KK / BK;

    int tid = threadIdx.x, lane = tid & 31, wid = tid >> 5;
    int wm = wid >> 2, wn = wid & 3;

    int ar0 = tid >> 2, as = tid & 3;
    bool avA[2]; const __nv_bfloat16 *AhP[2], *AlP[2];
    #pragma unroll
    for (int h = 0; h < 2; h++) {
        int slot = mbase + ar0 + h*64;
        avA[h] = slot < M_eff;
        int rr = avA[h] ? slot : mbase;
        AhP[h] = Ah_g + (size_t)rr*KK + as*8;
        AlP[h] = Al_g + (size_t)rr*KK + as*8;
    }
    // B: 32 rows x 16 chunks = 512 chunks; thread does chunk tid and tid+256
    int br0 = tid >> 4, bs0 = tid & 15;

    auto load_stage = [&](int s, int kt) {
        uint32_t st = sbase + (uint32_t)s*STAGE_BYTES;
        #pragma unroll
        for (int h = 0; h < 2; h++) {
            uint32_t d = a_off(ar0 + h*64, as);
            cpa16z(st + d,        AhP[h] + kt, avA[h]);
            cpa16z(st + 8192 + d, AlP[h] + kt, avA[h]);
        }
        #pragma unroll
        for (int h = 0; h < 2; h++) {
            int r = br0 + h*16;
            uint32_t d = b_off(r, bs0, 256);
            size_t src = (size_t)(kt + r)*D_DIM + nbase + bs0*8;
            cpa16(st + 16384 + d, Bh_g + src);
            cpa16(st + 24576 + d, Bl_g + src);
        }
        cpa_commit();
    };

    float c[4][4][4] = {};

    load_stage(0, 0);
    load_stage(1, BK);
    for (int t = 0; t < NT; t++) {
        int s = t % N_STAGE;
        if (t < NT - 1) cpa_wait1(); else cpa_wait0();
        __syncthreads();
        if (t + 2 < NT) load_stage((t + 2) % N_STAGE, (t + 2) * BK);

        uint32_t st = sbase + (uint32_t)s*STAGE_BYTES;
        #pragma unroll
        for (int ks = 0; ks < 2; ks++) {
            int k0 = ks * 16;
            int rr = k0 + (lane & 7) + ((lane >> 3) & 1) * 8;
            uint32_t bh[2][4], bl[2][4];
            #pragma unroll
            for (int h = 0; h < 2; h++) {
                int cc = wn*32 + h*16 + (lane >> 4) * 8;
                uint32_t boff = b_off(rr, cc >> 3, 256);
                ldsm_x4_t(bh[h], st + 16384 + boff);
                ldsm_x4_t(bl[h], st + 24576 + boff);
            }
            #pragma unroll
            for (int mt = 0; mt < 4; mt++) {
                int r = wm*64 + mt*16 + (lane & 15);
                int sA = (k0 >> 3) + (lane >> 4);
                uint32_t aoff = a_off(r, sA);
                uint32_t ah[4], al[4];
                ldsm_x4(ah, st + aoff);
                ldsm_x4(al, st + 8192 + aoff);
                #pragma unroll
                for (int nt = 0; nt < 4; nt++) {
                    mma16816(c[mt][nt], ah, &bh[nt>>1][(nt&1)*2]);
                    mma16816(c[mt][nt], ah, &bl[nt>>1][(nt&1)*2]);
                    mma16816(c[mt][nt], al, &bh[nt>>1][(nt&1)*2]);
                }
            }
        }
    }

    int r0 = lane >> 2, cb = (lane & 3) * 2;
    #pragma unroll
    for (int mt = 0; mt < 4; mt++) {
        #pragma unroll
        for (int p = 0; p < 2; p++) {
            int m = mbase + wm*64 + mt*16 + r0 + p*8;
            if (m >= M_eff) continue;
            if (expert_mode) {
                int tok = rows[m];
                float w = wv[m];
                float* orow = out + (size_t)tok*D_DIM;
                #pragma unroll
                for (int nt = 0; nt < 4; nt++) {
                    int n = nbase + wn*32 + nt*8 + cb;
                    atomicAdd(&orow[n],   c[mt][nt][2*p+0] * w);
                    atomicAdd(&orow[n+1], c[mt][nt][2*p+1] * w);
                }
            } else {
                float* orow = out + (size_t)m*D_DIM;
                #pragma unroll
                for (int nt = 0; nt < 4; nt++) {
                    int n = nbase + wn*32 + nt*8 + cb;
                    *(float2*)&orow[n] = make_float2(c[mt][nt][2*p+0], c[mt][nt][2*p+1]);
                }
            }
        }
    }
}

// ---------------- host launcher ----------------
extern "C" void kernel_launch(void* const* d_in, const int* in_sizes, int n_in,
                              void* d_out, int out_size)
{
    const float* x   = (const float*)d_in[0];
    const float* Wg  = (const float*)d_in[1];
    const float* W1  = (const float*)d_in[2];
    const float* W2  = (const float*)d_in[3];
    const float* W3  = (const float*)d_in[4];
    const float* Ws1 = (const float*)d_in[5];
    const float* Ws2 = (const float*)d_in[6];
    const float* Ws3 = (const float*)d_in[7];
    float* out = (float*)d_out;

    cudaFuncSetAttribute(up_mma,   cudaFuncAttributeMaxDynamicSharedMemorySize, DYN_SMEM);
    cudaFuncSetAttribute(down_mma, cudaFuncAttributeMaxDynamicSharedMemorySize, DYN_SMEM);

    void *xh, *xl, *w1h, *w1l, *w3h, *w3l, *w2h, *w2l;
    void *ws1h, *ws1l, *ws3h, *ws3l, *ws2h, *ws2l;
    cudaGetSymbolAddress(&xh,  g_Xh);  cudaGetSymbolAddress(&xl,  g_Xl);
    cudaGetSymbolAddress(&w1h, g_W1h); cudaGetSymbolAddress(&w1l, g_W1l);
    cudaGetSymbolAddress(&w3h, g_W3h); cudaGetSymbolAddress(&w3l, g_W3l);
    cudaGetSymbolAddress(&w2h, g_W2h); cudaGetSymbolAddress(&w2l, g_W2l);
    cudaGetSymbolAddress(&ws1h, g_Ws1h); cudaGetSymbolAddress(&ws1l, g_Ws1l);
    cudaGetSymbolAddress(&ws3h, g_Ws3h); cudaGetSymbolAddress(&ws3l, g_Ws3l);
    cudaGetSymbolAddress(&ws2h, g_Ws2h); cudaGetSymbolAddress(&ws2l, g_Ws2l);

    gate_kernel<<<T_TOK/8, 256>>>(x, Wg);
    dispatch_kernel<<<E_NUM, 256>>>();

    split_kernel<<<2048, 256>>>((const float4*)x,   (uint2*)xh,  (uint2*)xl,  (int)((size_t)T_TOK*D_DIM/4));
    split_kernel<<<2048, 256>>>((const float4*)W1,  (uint2*)w1h, (uint2*)w1l, (int)((size_t)E_NUM*D_DIM*H_DIM/4));
    split_kernel<<<2048, 256>>>((const float4*)W3,  (uint2*)w3h, (uint2*)w3l, (int)((size_t)E_NUM*D_DIM*H_DIM/4));
    split_kernel<<<2048, 256>>>((const float4*)W2,  (uint2*)w2h, (uint2*)w2l, (int)((size_t)E_NUM*H_DIM*D_DIM/4));
    split_kernel<<<2048, 256>>>((const float4*)Ws1, (uint2*)ws1h,(uint2*)ws1l,(int)((size_t)D_DIM*HS_DIM/4));
    split_kernel<<<2048, 256>>>((const float4*)Ws3, (uint2*)ws3h,(uint2*)ws3l,(int)((size_t)D_DIM*HS_DIM/4));
    split_kernel<<<2048, 256>>>((const float4*)Ws2, (uint2*)ws2h,(uint2*)ws2l,(int)((size_t)HS_DIM*D_DIM/4));

    // shared expert (dense) — down stores initialize every out element
    up_mma  <<<dim3(T_TOK/BM, HS_DIM/64, 1), 256, DYN_SMEM>>>(HS_DIM, 0);
    down_mma<<<dim3(T_TOK/BM, D_DIM/128, 1), 256, DYN_SMEM>>>(HS_DIM, 0, out);

    // routed experts
    up_mma  <<<dim3(CAP/BM, H_DIM/64, E_NUM), 256, DYN_SMEM>>>(H_DIM, 1);
    down_mma<<<dim3(CAP/BM, D_DIM/128, E_NUM), 256, DYN_SMEM>>>(H_DIM, 1, out);
}